// round 17
// baseline (speedup 1.0000x reference)
#include <cuda_runtime.h>
#include <cstdint>

#define B_ 8
#define D_ 128
#define T_ 4096
#define Q_ 30
#define C_ 1024
#define BT_ (B_ * T_)
#define NOUT (B_ * D_ * T_)

#define TM 128
#define TN 128
#define NCHUNK 8
#define THREADS 512
#define CAP 32
#define ROWSTRIDE 144

// smem layout (bytes)
#define OFF_AS 0                      // 65536  residual fp32 [k][row]
#define OFF_A8 65536                  // 18432  int8 residual plane, 128 x 144B
#define OFF_BB 83968                  // 36864  int8 B double buffer
#define BB_BUF 18432
#define OFF_C2 120832                 // 4096   per-code c2
#define OFF_ISC 124928                // 4096   per-code 1/sc
#define OFF_QM 129024                 // 2048   per-(row,quarter) max
#define OFF_QSUM 131072               // 2048   per-(row,quarter) abs-sum
#define OFF_SR 133120                 // 512    per-row invsr
#define OFF_DL 133632                 // 512    per-row delta
#define OFF_BI 134144                 // 512    per-row argmin
#define OFF_LR 134656                 // 128    loss partials
#define OFF_CT 134784                 // 512    candidate counts
#define OFF_CD 135296                 // 8192   candidate codes (128 x CAP u16)
#define SMEM_BYTES 143488

__device__ float g_c2[Q_ * C_];
__device__ float g_isc[Q_ * C_];
__device__ unsigned int g_gmax_u[Q_];   // max_c sum|c|  (float as uint, positives)
__device__ unsigned int g_imax_u[Q_];   // max_c 1/sc
__device__ double g_loss;
// int8 codebook: [q][code][k]
__device__ __align__(16) signed char g_bk8[(size_t)Q_ * C_ * D_];

__device__ __forceinline__ void cp16(uint32_t saddr, const void* g) {
    asm volatile("cp.async.cg.shared.global [%0], [%1], 16;\n" ::"r"(saddr), "l"(g));
}
#define CP_COMMIT asm volatile("cp.async.commit_group;\n" ::: "memory")
#define CP_WAIT0 asm volatile("cp.async.wait_group 0;\n" ::: "memory")

__device__ __forceinline__ void ldm4(uint32_t& r0, uint32_t& r1, uint32_t& r2,
                                     uint32_t& r3, uint32_t addr) {
    asm volatile("ldmatrix.sync.aligned.m8n8.x4.shared.b16 {%0,%1,%2,%3}, [%4];"
                 : "=r"(r0), "=r"(r1), "=r"(r2), "=r"(r3)
                 : "r"(addr));
}

__device__ __forceinline__ void mma16832s8(int& c0, int& c1, int& c2, int& c3,
                                           uint32_t a0, uint32_t a1, uint32_t a2,
                                           uint32_t a3, uint32_t b0, uint32_t b1) {
    asm volatile(
        "mma.sync.aligned.m16n8k32.row.col.s32.s8.s8.s32 "
        "{%0,%1,%2,%3}, {%4,%5,%6,%7}, {%8,%9}, {%0,%1,%2,%3};"
        : "+r"(c0), "+r"(c1), "+r"(c2), "+r"(c3)
        : "r"(a0), "r"(a1), "r"(a2), "r"(a3), "r"(b0), "r"(b1));
}

// ---- c2: EXACT R14-champion summation order (contiguous float4 + shfl_down) ----
__global__ void k_c2(const float* __restrict__ cb) {
    int code = blockIdx.x * 8 + (threadIdx.x >> 5);
    int lane = threadIdx.x & 31;
    float4 v = *(const float4*)(cb + (size_t)code * D_ + lane * 4);
    float s = v.x * v.x + v.y * v.y + v.z * v.z + v.w * v.w;
#pragma unroll
    for (int o = 16; o; o >>= 1) s += __shfl_down_sync(0xffffffffu, s, o);
    if (lane == 0) g_c2[code] = s;
    if (blockIdx.x == 0 && threadIdx.x == 0) g_loss = 0.0;
}

// ---- int8 quantization prep (scales + per-q maxima); does NOT touch c2 ----
__global__ void k_prep8(const float* __restrict__ cb) {
    int qc = blockIdx.x * 8 + (threadIdx.x >> 5);  // one warp per code
    int lane = threadIdx.x & 31;
    const float* cp = cb + (size_t)qc * D_;
    float v[4];
    float amax = 0.f, asum = 0.f;
#pragma unroll
    for (int i = 0; i < 4; ++i) {
        v[i] = cp[lane + 32 * i];
        float a = fabsf(v[i]);
        amax = fmaxf(amax, a);
        asum += a;
    }
#pragma unroll
    for (int o = 16; o; o >>= 1) {
        amax = fmaxf(amax, __shfl_xor_sync(0xffffffffu, amax, o));
        asum += __shfl_xor_sync(0xffffffffu, asum, o);
    }
    amax = fmaxf(amax, 1e-20f);
    float sc = 126.f / amax;
    signed char* dst = g_bk8 + (size_t)qc * D_;
#pragma unroll
    for (int i = 0; i < 4; ++i)
        dst[lane + 32 * i] = (signed char)__float2int_rn(v[i] * sc);
    if (lane == 0) {
        g_isc[qc] = amax * (1.f / 126.f);
        int q = qc >> 10;
        atomicMax(&g_gmax_u[q], __float_as_uint(asum));
        atomicMax(&g_imax_u[q], __float_as_uint(amax * (1.f / 126.f)));
    }
}

// ---- fused VQ: int8 mma.sync screening + exact fp32 candidate rescore ----
__global__ __launch_bounds__(THREADS, 1) void k_vq(const float* __restrict__ x,
                                                   const float* __restrict__ cb_all,
                                                   float* __restrict__ out) {
    extern __shared__ char smem[];
    float* As = (float*)(smem + OFF_AS);
    float* c2s = (float*)(smem + OFF_C2);
    float* iscs = (float*)(smem + OFF_ISC);
    float* qmaxs = (float*)(smem + OFF_QM);
    float* qsums = (float*)(smem + OFF_QSUM);
    float* dinvsr = (float*)(smem + OFF_SR);
    float* ddelta = (float*)(smem + OFF_DL);
    int* bidx = (int*)(smem + OFF_BI);
    double* lred = (double*)(smem + OFF_LR);
    int* ccnt = (int*)(smem + OFF_CT);
    unsigned short* cand = (unsigned short*)(smem + OFF_CD);

    const int tid = threadIdx.x;
    const int lane = tid & 31;
    const int w = tid >> 5;        // 0..15
    const int wr = w & 7;          // row-warp 0..7
    const int whalf = w >> 3;      // code half 0/1
    const int bt0 = blockIdx.x * TM;
    const int b = bt0 / T_;
    const int t0 = bt0 % T_;
    const float* xb = x + (size_t)b * D_ * T_ + t0;

    const uint32_t sBase = (uint32_t)__cvta_generic_to_shared(smem);
    const uint32_t sA8 = sBase + OFF_A8;
    const uint32_t sBB = sBase + OFF_BB;

    const int arow = 16 * wr + (lane & 15);
    const uint32_t aoff = (uint32_t)(arow * ROWSTRIDE + ((lane >= 16) ? 16 : 0));
    const int brow = (lane & 7) + ((lane >= 16) ? 8 : 0);
    const uint32_t boff =
        (uint32_t)((whalf * 64 + brow) * ROWSTRIDE + ((lane & 8) ? 16 : 0));

    // rows owned by this warp's D fragments
    const int R0 = 16 * wr + (lane >> 2);
    const int R1 = R0 + 8;

    // update/quant mapping: 512 thr = (row, quarter)
    const int urow = tid & 127;
    const int uq = tid >> 7;       // 0..3 -> 32 d's each
    const int udbase = uq * 32;

    // load residual tile As[k*128+row]
    for (int i = 0; i < 32; ++i) {
        int idx = i * THREADS + tid;
        int d = idx >> 7, tc = idx & 127;
        As[d * 128 + tc] = xb[(size_t)d * T_ + tc];
    }
    if (tid < TM) ccnt[tid] = 0;
    __syncthreads();

    // initial per-quarter max/abs-sum of residual
    {
        float m = 0.f, s = 0.f;
#pragma unroll 8
        for (int d = udbase; d < udbase + 32; ++d) {
            float a = fabsf(As[d * 128 + urow]);
            m = fmaxf(m, a);
            s += a;
        }
        qmaxs[urow * 4 + uq] = m;
        qsums[urow * 4 + uq] = s;
    }

    // prefetch q=0 chunk 0 (128 codes x 128B = 1024 x 16B units)
    {
#pragma unroll
        for (int it = 0; it < 2; ++it) {
            int u = it * THREADS + tid;
            int code = u >> 3, blk = u & 7;
            cp16(sBB + code * ROWSTRIDE + blk * 16,
                 g_bk8 + (size_t)code * D_ + blk * 16);
        }
        CP_COMMIT;
    }

    double dloss = 0.0;

    for (int q = 0; q < Q_; ++q) {
        const float* cbq = cb_all + (size_t)q * C_ * D_;
        for (int i = tid; i < C_; i += THREADS) {
            c2s[i] = g_c2[q * C_ + i];
            iscs[i] = g_isc[q * C_ + i];
        }
        const float Gmax = __uint_as_float(g_gmax_u[q]);
        const float Imax = __uint_as_float(g_imax_u[q]);
        __syncthreads();  // qred (from init/prev update), ccnt reset visible

        // ---- quantize residual rows to int8 + per-row delta/invsr ----
        {
            float m = fmaxf(fmaxf(qmaxs[urow * 4 + 0], qmaxs[urow * 4 + 1]),
                            fmaxf(qmaxs[urow * 4 + 2], qmaxs[urow * 4 + 3]));
            float Ar = qsums[urow * 4 + 0] + qsums[urow * 4 + 1] +
                       qsums[urow * 4 + 2] + qsums[urow * 4 + 3];
            m = fmaxf(m, 1e-20f);
            float sr = 126.f / m;
            float invsr = m * (1.f / 126.f);
            if (uq == 0) {
                dinvsr[urow] = invsr;
                // delta = 2 * E_score * 1.05 = 4.2 * E_dot (hard bound + margin)
                ddelta[urow] = 4.2f * (0.5f * Imax * Ar + 0.5f * Gmax * invsr +
                                       96.f * Imax * invsr);
            }
            uint32_t* d32 = (uint32_t*)(smem + OFF_A8 + urow * ROWSTRIDE + udbase);
#pragma unroll
            for (int i = 0; i < 8; ++i) {
                int d = udbase + 4 * i;
                int v0 = __float2int_rn(As[(d + 0) * 128 + urow] * sr);
                int v1 = __float2int_rn(As[(d + 1) * 128 + urow] * sr);
                int v2 = __float2int_rn(As[(d + 2) * 128 + urow] * sr);
                int v3 = __float2int_rn(As[(d + 3) * 128 + urow] * sr);
                d32[i] = (uint32_t)(v0 & 255) | ((uint32_t)(v1 & 255) << 8) |
                         ((uint32_t)(v2 & 255) << 16) | ((uint32_t)(v3 & 255) << 24);
            }
        }
        __syncthreads();  // A8, dinvsr, ddelta, c2s, iscs ready

        // hoist A fragments (4 k-steps, invariant across chunks)
        uint32_t afr[4][4];
#pragma unroll
        for (int kk = 0; kk < 4; ++kk)
            ldm4(afr[kk][0], afr[kk][1], afr[kk][2], afr[kk][3],
                 sA8 + aoff + kk * 32);

        const float invsr0 = dinvsr[R0], invsr1 = dinvsr[R1];
        const float delta0 = ddelta[R0], delta1 = ddelta[R1];
        const float tt0 = -2.f * invsr0, tt1 = -2.f * invsr1;

        const float INF = __int_as_float(0x7f800000);
        float rm0 = INF, rm1 = INF;

        for (int ch = 0; ch < NCHUNK; ++ch) {
            CP_WAIT0;
            __syncthreads();

            // prefetch next chunk of this q, or chunk 0 of q+1
            if (ch + 1 < NCHUNK || q + 1 < Q_) {
                const signed char* srcn = (ch + 1 < NCHUNK)
                    ? g_bk8 + ((size_t)q * C_ + (ch + 1) * TN) * D_
                    : g_bk8 + ((size_t)(q + 1)) * C_ * D_;
                uint32_t dstb = sBB + ((ch + 1) & 1) * BB_BUF;
#pragma unroll
                for (int it = 0; it < 2; ++it) {
                    int u = it * THREADS + tid;
                    int code = u >> 3, blk = u & 7;
                    cp16(dstb + code * ROWSTRIDE + blk * 16,
                         srcn + (size_t)code * D_ + blk * 16);
                }
                CP_COMMIT;
            }

            const uint32_t bufB = sBB + (ch & 1) * BB_BUF;

            int c[8][4];
#pragma unroll
            for (int nt = 0; nt < 8; ++nt)
#pragma unroll
                for (int j = 0; j < 4; ++j) c[nt][j] = 0;

#pragma unroll
            for (int kk = 0; kk < 4; ++kk) {
#pragma unroll
                for (int ntp = 0; ntp < 4; ++ntp) {
                    uint32_t b0[4];
                    uint32_t bbase = bufB + boff + ntp * 16 * ROWSTRIDE + kk * 32;
                    ldm4(b0[0], b0[1], b0[2], b0[3], bbase);
                    int* cl = c[2 * ntp];
                    int* ch2 = c[2 * ntp + 1];
                    mma16832s8(cl[0], cl[1], cl[2], cl[3],
                               afr[kk][0], afr[kk][1], afr[kk][2], afr[kk][3],
                               b0[0], b0[1]);
                    mma16832s8(ch2[0], ch2[1], ch2[2], ch2[3],
                               afr[kk][0], afr[kk][1], afr[kk][2], afr[kk][3],
                               b0[2], b0[3]);
                }
            }

            // pass 1: chunk min (scores: c2 - 2*invsr*invsc*idot)
            float cm0 = INF, cm1 = INF;
            const int cgb = ch * TN + whalf * 64 + 2 * (lane & 3);
#pragma unroll
            for (int nt = 0; nt < 8; ++nt) {
                int cg = cgb + nt * 8;
                float ia = iscs[cg], ib = iscs[cg + 1];
                float c2a = c2s[cg], c2b = c2s[cg + 1];
                cm0 = fminf(cm0, fminf(fmaf(tt0 * ia, (float)c[nt][0], c2a),
                                       fmaf(tt0 * ib, (float)c[nt][1], c2b)));
                cm1 = fminf(cm1, fminf(fmaf(tt1 * ia, (float)c[nt][2], c2a),
                                       fmaf(tt1 * ib, (float)c[nt][3], c2b)));
            }
#pragma unroll
            for (int m = 1; m <= 2; m <<= 1) {
                cm0 = fminf(cm0, __shfl_xor_sync(0xffffffffu, cm0, m));
                cm1 = fminf(cm1, __shfl_xor_sync(0xffffffffu, cm1, m));
            }
            rm0 = fminf(rm0, cm0);
            rm1 = fminf(rm1, cm1);
            float th0 = rm0 + delta0, th1 = rm1 + delta1;

            // pass 2: recompute + append only when chunk can contribute
            if (cm0 < th0) {
#pragma unroll
                for (int nt = 0; nt < 8; ++nt) {
                    int cg = cgb + nt * 8;
                    float s0 = fmaf(tt0 * iscs[cg], (float)c[nt][0], c2s[cg]);
                    float s1 = fmaf(tt0 * iscs[cg + 1], (float)c[nt][1], c2s[cg + 1]);
                    if (s0 < th0) { int p = atomicAdd(&ccnt[R0], 1); if (p < CAP) cand[R0 * CAP + p] = (unsigned short)cg; }
                    if (s1 < th0) { int p = atomicAdd(&ccnt[R0], 1); if (p < CAP) cand[R0 * CAP + p] = (unsigned short)(cg + 1); }
                }
            }
            if (cm1 < th1) {
#pragma unroll
                for (int nt = 0; nt < 8; ++nt) {
                    int cg = cgb + nt * 8;
                    float s2 = fmaf(tt1 * iscs[cg], (float)c[nt][2], c2s[cg]);
                    float s3 = fmaf(tt1 * iscs[cg + 1], (float)c[nt][3], c2s[cg + 1]);
                    if (s2 < th1) { int p = atomicAdd(&ccnt[R1], 1); if (p < CAP) cand[R1 * CAP + p] = (unsigned short)cg; }
                    if (s3 < th1) { int p = atomicAdd(&ccnt[R1], 1); if (p < CAP) cand[R1 * CAP + p] = (unsigned short)(cg + 1); }
                }
            }
        }
        __syncthreads();  // candidates visible

        // ---- exact fp32 rescore, split: whalf==0 -> R0, whalf==1 -> R1 ----
        //      (byte-identical arithmetic to the 2550us champion)
        {
            int r = whalf ? R1 : R0;
            int n = ccnt[r];
            bool ovf = n > CAP;
            if (ovf) n = C_;  // guaranteed-correct fallback
            float bv = INF;
            int bi = 0x7fffffff;
            for (int i = lane & 3; i < n; i += 4) {
                int code = ovf ? i : (int)cand[r * CAP + i];
                const float4* cp4 = (const float4*)(cbq + (size_t)code * D_);
                float s = 0.f;
#pragma unroll 8
                for (int dq = 0; dq < 32; ++dq) {
                    float4 cv = cp4[dq];
                    s = fmaf(As[(4 * dq + 0) * 128 + r], cv.x, s);
                    s = fmaf(As[(4 * dq + 1) * 128 + r], cv.y, s);
                    s = fmaf(As[(4 * dq + 2) * 128 + r], cv.z, s);
                    s = fmaf(As[(4 * dq + 3) * 128 + r], cv.w, s);
                }
                float scv = fmaf(-2.f, s, c2s[code]);
                if (scv < bv || (scv == bv && code < bi)) { bv = scv; bi = code; }
            }
#pragma unroll
            for (int m = 1; m <= 2; m <<= 1) {
                float ov = __shfl_xor_sync(0xffffffffu, bv, m);
                int oi = __shfl_xor_sync(0xffffffffu, bi, m);
                if (ov < bv || (ov == bv && oi < bi)) { bv = ov; bi = oi; }
            }
            if ((lane & 3) == 0) bidx[r] = bi;
        }
        __syncthreads();  // bidx ready; screening reads of A8 done

        // ---- fused: residual update + loss + per-quarter max/sum for next q ----
        {
            const float4* cp4 =
                (const float4*)(cbq + (size_t)bidx[urow] * D_ + udbase);
            float ls = 0.f, qm = 0.f, qs = 0.f;
#pragma unroll
            for (int i = 0; i < 8; ++i) {
                float4 cv = cp4[i];
                int d = udbase + 4 * i;
                float n0 = As[(d + 0) * 128 + urow] - cv.x;
                float n1 = As[(d + 1) * 128 + urow] - cv.y;
                float n2 = As[(d + 2) * 128 + urow] - cv.z;
                float n3 = As[(d + 3) * 128 + urow] - cv.w;
                As[(d + 0) * 128 + urow] = n0;
                As[(d + 1) * 128 + urow] = n1;
                As[(d + 2) * 128 + urow] = n2;
                As[(d + 3) * 128 + urow] = n3;
                ls += n0 * n0 + n1 * n1 + n2 * n2 + n3 * n3;
                float a0 = fabsf(n0), a1 = fabsf(n1), a2 = fabsf(n2), a3 = fabsf(n3);
                qm = fmaxf(qm, fmaxf(fmaxf(a0, a1), fmaxf(a2, a3)));
                qs += a0 + a1 + a2 + a3;
            }
            qmaxs[urow * 4 + uq] = qm;
            qsums[urow * 4 + uq] = qs;
            dloss += (double)ls;
        }
        if (tid < TM) ccnt[tid] = 0;  // after rescore read, before next q
        // next q's top barrier orders As/qred/ccnt for the quant phase
    }

    __syncthreads();
    // quantized = x - residual_final, straight [B,D,T]
    for (int i = 0; i < 32; ++i) {
        int idx = i * THREADS + tid;
        int d = idx >> 7, tc = idx & 127;
        size_t gi = (size_t)d * T_ + tc;
        out[(size_t)b * D_ * T_ + t0 + gi] = xb[gi] - As[d * 128 + tc];
    }

    // loss reduce
    double v = dloss;
#pragma unroll
    for (int o = 16; o; o >>= 1) v += __shfl_down_sync(0xffffffffu, v, o);
    if (lane == 0) lred[w] = v;
    __syncthreads();
    if (tid == 0) {
        double tot = 0.0;
#pragma unroll
        for (int i = 0; i < 16; ++i) tot += lred[i];
        atomicAdd(&g_loss, tot);
    }
}

__global__ void k_loss(float* __restrict__ out, int out_size) {
    if (out_size > NOUT) out[NOUT] = (float)(g_loss / (double)((size_t)BT_ * D_));
}

extern "C" void kernel_launch(void* const* d_in, const int* in_sizes, int n_in,
                              void* d_out, int out_size) {
    const float* x = (const float*)d_in[0];
    const float* cb = (const float*)d_in[1];
    float* out = (float*)d_out;

    cudaFuncSetAttribute(k_vq, cudaFuncAttributeMaxDynamicSharedMemorySize, SMEM_BYTES);

    k_c2<<<(Q_ * C_) / 8, 256>>>(cb);
    k_prep8<<<(Q_ * C_) / 8, 256>>>(cb);
    k_vq<<<BT_ / TM, THREADS, SMEM_BYTES>>>(x, cb, out);
    k_loss<<<1, 1>>>(out, out_size);
}